// round 12
// baseline (speedup 1.0000x reference)
#include <cuda_runtime.h>

#define C_IN   64
#define C_OUT  128
#define NKER   16
#define BEV_H  512
#define BEV_W  512
#define HW     (BEV_H * BEV_W)
#define MAXN   65536
#define NBX    1024        // (b,x) bins
#define CAPX   1024        // max points per (b,x) bin (fixed region)
#define PPB    64          // points per chunk, phase 1
#define FBLK   40          // k_feat blocks per h bin (grid-strided)
#define CG     8           // channels per k_bev block
#define NCG    (C_OUT / CG)
#define CPITCH 516         // c-major tile pitch: 516 mod 32 == 4 -> conflict-free

// ---------------- scratch (__device__ globals; no allocation) ----------------
// Zero-initialized at load; k_bev's done-counter resets ALL cursors after the
// last consumer of each bin, so every graph replay starts from zeroed state.
__device__ int   d_curH[NKER];
__device__ int   d_curX[NBX];
__device__ int   d_doneX[NBX];
__device__ int   d_binH[NKER * MAXN];            // point index, region per h
__device__ int   d_binX[NBX * CAPX];             // packed (pt << 9) | z
__device__ float d_fbuf[(size_t)MAXN * C_OUT];   // per-point features post-GEMM

// ---------------- packed f32x2 helpers ----------------
__device__ __forceinline__ unsigned long long pack2(float lo, float hi) {
    unsigned long long r;
    asm("mov.b64 %0, {%1, %2};" : "=l"(r) : "f"(lo), "f"(hi));
    return r;
}
__device__ __forceinline__ void unpack2(unsigned long long v, float& lo, float& hi) {
    asm("mov.b64 {%0, %1}, %2;" : "=f"(lo), "=f"(hi) : "l"(v));
}
__device__ __forceinline__ unsigned long long fma2(unsigned long long a,
                                                   unsigned long long b,
                                                   unsigned long long c) {
    unsigned long long d;
    asm("fma.rn.f32x2 %0, %1, %2, %3;" : "=l"(d) : "l"(a), "l"(b), "l"(c));
    return d;
}

// ---------------------------------------------------------------------------
// Fused binning: block-level smem histogram + rank, one global reservation
// per non-empty bin per block, direct scatter into fixed bin regions.
// ---------------------------------------------------------------------------
__global__ __launch_bounds__(256)
void k_bin(const int* __restrict__ coords, int n)
{
    __shared__ int histH[NKER],  baseH[NKER];
    __shared__ int histX[NBX],   baseX[NBX];

    const int tid = threadIdx.x;
    {
        int4* h4 = (int4*)histX;
        h4[tid] = make_int4(0, 0, 0, 0);
    }
    if (tid < NKER) histH[tid] = 0;
    __syncthreads();

    int i = blockIdx.x * 256 + tid;
    int h = 0, bx = 0, z = 0, rH = 0, rX = 0;
    bool valid = (i < n);
    if (valid) {
        int4 c = ((const int4*)coords)[i];           // [x, h, z, b]
        h  = c.y & (NKER - 1);
        bx = (c.w << 9) | c.x;
        z  = c.z;
        rH = atomicAdd(&histH[h], 1);
        rX = atomicAdd(&histX[bx], 1);
    }
    __syncthreads();

    if (tid < NKER && histH[tid] > 0)
        baseH[tid] = atomicAdd(&d_curH[tid], histH[tid]);
    for (int j = tid; j < NBX; j += 256)
        if (histX[j] > 0)
            baseX[j] = atomicAdd(&d_curX[j], histX[j]);
    __syncthreads();

    if (valid) {
        d_binH[h * MAXN + baseH[h] + rH] = i;
        int slot = baseX[bx] + rX;
        if (slot < CAPX)
            d_binX[bx * CAPX + slot] = (i << 9) | z;
    }
    cudaTriggerProgrammaticLaunchCompletion();
}

// ---------------------------------------------------------------------------
// Phase 1: per-point GEMV. EARLY TRIGGER: fires right after the gridsync on
// k_bin, so k_bev can launch and stream its zero-stores while this grid's
// GEMV is still running. (Trigger after gridsync also guarantees k_bin's
// writes are visible to k_bev's pre-gridsync reads of d_binX/d_curX.)
// ---------------------------------------------------------------------------
__global__ __launch_bounds__(256)
void k_feat(const float* __restrict__ feats,
            const float* __restrict__ kern)
{
    const int bin = blockIdx.y;

    __shared__ float Ks[C_IN * C_OUT];               // 32 KB
    {
        const float4* g = (const float4*)(kern + (size_t)bin * C_IN * C_OUT);
        float4* sp = (float4*)Ks;
        for (int i = threadIdx.x; i < (C_IN * C_OUT) / 4; i += 256)
            sp[i] = g[i];
    }

    cudaGridDependencySynchronize();                 // wait for k_bin results
    cudaTriggerProgrammaticLaunchCompletion();       // let k_bev launch NOW
    __syncthreads();

    const int cnt = d_curH[bin];
    const int* binp = d_binH + bin * MAXN;
    const int warp = threadIdx.x >> 5;
    const int lane = threadIdx.x & 31;

    for (int bstart = blockIdx.x * PPB; bstart < cnt; bstart += FBLK * PPB) {
        const int bend = min(bstart + PPB, cnt);

        for (int g0 = bstart + warp * 4; g0 < bend; g0 += 32) {
            const int nv = min(4, bend - g0);
            float2 fv[4];
            int    pts[4];

            #pragma unroll
            for (int p = 0; p < 4; p++) {
                if (p < nv) {
                    pts[p] = binp[g0 + p];
                    fv[p]  = ((const float2*)(feats + (size_t)pts[p] * C_IN))[lane];
                } else {
                    fv[p] = make_float2(0.f, 0.f);
                    pts[p] = 0;
                }
            }

            unsigned long long accA[4], accB[4];
            #pragma unroll
            for (int p = 0; p < 4; p++) { accA[p] = 0ull; accB[p] = 0ull; }

            #pragma unroll
            for (int c = 0; c < C_IN; c++) {
                float4 k = *(const float4*)(Ks + c * C_OUT + 4 * lane);
                unsigned long long kA = pack2(k.x, k.y);
                unsigned long long kB = pack2(k.z, k.w);
                #pragma unroll
                for (int p = 0; p < 4; p++) {
                    float f = __shfl_sync(0xffffffffu,
                                          (c & 1) ? fv[p].y : fv[p].x, c >> 1);
                    unsigned long long ff = pack2(f, f);
                    accA[p] = fma2(ff, kA, accA[p]);
                    accB[p] = fma2(ff, kB, accB[p]);
                }
            }

            #pragma unroll
            for (int p = 0; p < 4; p++) {
                if (p < nv) {
                    float4 v;
                    unpack2(accA[p], v.x, v.y);
                    unpack2(accB[p], v.z, v.w);
                    *(float4*)(d_fbuf + (size_t)pts[p] * C_OUT + 4 * lane) = v;
                }
            }
        }
    }
}

// ---------------------------------------------------------------------------
// Phase 2: row-owner scatter, 8 channels per block.
// PRELUDE (before gridsync, overlaps k_feat): build zmask from bin list, then
// stream zero-stores for ALL untouched 4-z chunks (~92% of output volume)
// and zero the touched smem cells. Then gridsync (k_feat done), smem-atomic
// accumulate, and store ONLY the touched chunks.
// Done-counter: 16th finisher of a bin resets curX/doneX/curH.
// ---------------------------------------------------------------------------
__global__ __launch_bounds__(256)
void k_bev(float* __restrict__ out)
{
    __shared__ float tile[CG * CPITCH];              // 16.5 KB
    __shared__ unsigned int zmask[4];                // 128 chunk bits

    const int bin = blockIdx.y;
    const int c0  = blockIdx.x << 3;
    const int b   = bin >> 9;
    const int x   = bin & 511;
    const int tid = threadIdx.x;

    if (tid < 4) zmask[tid] = 0u;
    __syncthreads();

    int cnt = d_curX[bin];
    if (cnt > CAPX) cnt = CAPX;
    const int* binp = d_binX + bin * CAPX;

    // prelude A: mark touched 4-z chunks
    for (int p = tid; p < cnt; p += 256) {
        int z = binp[p] & 511;
        atomicOr(&zmask[z >> 7], 1u << ((z >> 2) & 31));
    }
    __syncthreads();

    // prelude B: stream zeros for untouched chunks (global), zero touched
    // chunks in smem. j is per-thread invariant; each thread owns 4 channels.
    const int  j  = tid & 127;
    const int  cb = tid >> 7;
    const bool touched = (zmask[j >> 5] >> (j & 31)) & 1u;
    float4* o4 = (float4*)(out + (((size_t)(b * C_OUT + c0)) * BEV_H + x) * BEV_W);
    const float4 zero4 = make_float4(0.f, 0.f, 0.f, 0.f);
    #pragma unroll
    for (int k = 0; k < 4; k++) {
        int c = cb + 2 * k;
        if (!touched) __stcs(&o4[(size_t)c * (HW / 4) + j], zero4);
        else          *(float4*)&tile[c * CPITCH + 4 * j] = zero4;
    }

    cudaGridDependencySynchronize();                 // wait for k_feat's f_buf
    __syncthreads();

    // accumulate (quarter-warp = one point, lane = channel; conflict-free)
    const int qwid = tid >> 3;
    const int ql   = tid & 7;
    for (int p = qwid; p < cnt; p += 32) {
        int e  = binp[p];
        int pt = e >> 9;
        int z  = e & 511;
        float v = d_fbuf[(size_t)pt * C_OUT + c0 + ql];
        atomicAdd(&tile[ql * CPITCH + z], v);
    }
    __syncthreads();

    // store touched chunks only
    if (touched) {
        #pragma unroll
        for (int k = 0; k < 4; k++) {
            int c = cb + 2 * k;
            __stcs(&o4[(size_t)c * (HW / 4) + j], *(float4*)&tile[c * CPITCH + 4 * j]);
        }
    }

    // last of this bin's 16 blocks resets its cursors (all have read cnt,
    // and k_feat is fully complete past the gridsync above)
    if (tid == 0) {
        int dn = atomicAdd(&d_doneX[bin], 1);
        if (dn == NCG - 1) {
            d_curX[bin] = 0;
            d_doneX[bin] = 0;
            if (bin < NKER) d_curH[bin] = 0;
        }
    }
}

// ---------------------------------------------------------------------------
// Launch (PDL chain: k_bin -> k_feat (early trigger) -> k_bev)
// ---------------------------------------------------------------------------
extern "C" void kernel_launch(void* const* d_in, const int* in_sizes, int n_in,
                              void* d_out, int out_size)
{
    const int*   coords = (const int*)  d_in[0];   // [N,4] int32
    const float* feats  = (const float*)d_in[1];   // [N,64] f32
    const float* kern   = (const float*)d_in[2];   // [16,64,128] f32
    float*       out    = (float*)d_out;           // [2,128,512,512] f32

    int n = in_sizes[0] / 4;
    if (n > MAXN) n = MAXN;

    k_bin<<<(n + 255) / 256, 256>>>(coords, n);

    cudaLaunchAttribute attrs[1];
    attrs[0].id = cudaLaunchAttributeProgrammaticStreamSerialization;
    attrs[0].val.programmaticStreamSerializationAllowed = 1;

    {   // k_feat with PDL (smem preload overlaps k_bin tail; triggers early)
        cudaLaunchConfig_t cfg = {};
        cfg.gridDim  = dim3(FBLK, NKER);
        cfg.blockDim = dim3(256);
        cfg.stream   = 0;
        cfg.attrs    = attrs;
        cfg.numAttrs = 1;
        cudaLaunchKernelEx(&cfg, k_feat, feats, kern);
    }
    {   // k_bev with PDL (zero-store prelude overlaps k_feat's GEMV)
        cudaLaunchConfig_t cfg = {};
        cfg.gridDim  = dim3(NCG, NBX);
        cfg.blockDim = dim3(256);
        cfg.stream   = 0;
        cfg.attrs    = attrs;
        cfg.numAttrs = 1;
        cudaLaunchKernelEx(&cfg, k_bev, out);
    }
}

// round 13
// speedup vs baseline: 1.4388x; 1.4388x over previous
#include <cuda_runtime.h>

#define C_IN   64
#define C_OUT  128
#define NKER   16
#define BEV_H  512
#define BEV_W  512
#define HW     (BEV_H * BEV_W)
#define MAXN   65536
#define NBX    1024        // (b,x) bins
#define CAPX   1024        // max points per (b,x) bin (fixed region)
#define PPB    64          // points per chunk, phase 1
#define FBLK   40          // k_feat blocks per h bin (grid-strided)
#define CG     8           // channels per k_bev block
#define NCG    (C_OUT / CG)
#define ZPITCH 9           // z-major tile pitch (floats): 8 ch + 1 pad

// ---------------- scratch (__device__ globals; no allocation) ----------------
// Zero-initialized at load; k_bev's done-counter resets ALL cursors after the
// last consumer of each bin, so every graph replay starts from zeroed state.
__device__ int   d_curH[NKER];
__device__ int   d_curX[NBX];
__device__ int   d_doneX[NBX];
__device__ int   d_binH[NKER * MAXN];            // point index, region per h
__device__ int   d_binX[NBX * CAPX];             // packed (pt << 9) | z
__device__ float d_fbuf[(size_t)MAXN * C_OUT];   // per-point features post-GEMM

// ---------------- packed f32x2 helpers ----------------
__device__ __forceinline__ unsigned long long pack2(float lo, float hi) {
    unsigned long long r;
    asm("mov.b64 %0, {%1, %2};" : "=l"(r) : "f"(lo), "f"(hi));
    return r;
}
__device__ __forceinline__ void unpack2(unsigned long long v, float& lo, float& hi) {
    asm("mov.b64 {%0, %1}, %2;" : "=f"(lo), "=f"(hi) : "l"(v));
}
__device__ __forceinline__ unsigned long long fma2(unsigned long long a,
                                                   unsigned long long b,
                                                   unsigned long long c) {
    unsigned long long d;
    asm("fma.rn.f32x2 %0, %1, %2, %3;" : "=l"(d) : "l"(a), "l"(b), "l"(c));
    return d;
}

// ---------------------------------------------------------------------------
// Fused binning: 512 threads x 2 points/thread -> 40 blocks (4x fewer global
// reservation atomics on d_curH/d_curX than 157 blocks). Block-level smem
// histogram + rank, one reservation per non-empty bin per block, scatter.
// ---------------------------------------------------------------------------
__global__ __launch_bounds__(512)
void k_bin(const int* __restrict__ coords, int n)
{
    __shared__ int histH[NKER],  baseH[NKER];
    __shared__ int histX[NBX],   baseX[NBX];

    const int tid = threadIdx.x;
    if (tid < 256) {
        int4* h4 = (int4*)histX;
        h4[tid] = make_int4(0, 0, 0, 0);             // 1024 ints
    }
    if (tid < NKER) histH[tid] = 0;
    __syncthreads();

    int  idx[2];
    int  h[2], bx[2], z[2], rH[2], rX[2];
    bool valid[2];
    #pragma unroll
    for (int s = 0; s < 2; s++) {
        int i = blockIdx.x * 1024 + s * 512 + tid;
        idx[s] = i;
        valid[s] = (i < n);
        if (valid[s]) {
            int4 c = ((const int4*)coords)[i];       // [x, h, z, b]
            h[s]  = c.y & (NKER - 1);
            bx[s] = (c.w << 9) | c.x;
            z[s]  = c.z;
            rH[s] = atomicAdd(&histH[h[s]], 1);
            rX[s] = atomicAdd(&histX[bx[s]], 1);
        }
    }
    __syncthreads();

    if (tid < NKER && histH[tid] > 0)
        baseH[tid] = atomicAdd(&d_curH[tid], histH[tid]);
    for (int j = tid; j < NBX; j += 512)
        if (histX[j] > 0)
            baseX[j] = atomicAdd(&d_curX[j], histX[j]);
    __syncthreads();

    #pragma unroll
    for (int s = 0; s < 2; s++) {
        if (valid[s]) {
            d_binH[h[s] * MAXN + baseH[h[s]] + rH[s]] = idx[s];
            int slot = baseX[bx[s]] + rX[s];
            if (slot < CAPX)
                d_binX[bx[s] * CAPX + slot] = (idx[s] << 9) | z[s];
        }
    }
    cudaTriggerProgrammaticLaunchCompletion();
}

// ---------------------------------------------------------------------------
// Phase 1 (R7 shape): per-point GEMV  f_buf[pt][c] = feats[pt] . K[h][.][c]
// Grid (FBLK, NKER), grid-strided. Kernel slice staged into SMEM BEFORE the
// PDL grid sync, overlapping k_bin's tail.
// ---------------------------------------------------------------------------
__global__ __launch_bounds__(256)
void k_feat(const float* __restrict__ feats,
            const float* __restrict__ kern)
{
    const int bin = blockIdx.y;

    __shared__ float Ks[C_IN * C_OUT];               // 32 KB
    {
        const float4* g = (const float4*)(kern + (size_t)bin * C_IN * C_OUT);
        float4* sp = (float4*)Ks;
        for (int i = threadIdx.x; i < (C_IN * C_OUT) / 4; i += 256)
            sp[i] = g[i];
    }

    cudaGridDependencySynchronize();                 // wait for k_bin results
    __syncthreads();

    const int cnt = d_curH[bin];
    const int* binp = d_binH + bin * MAXN;
    const int warp = threadIdx.x >> 5;
    const int lane = threadIdx.x & 31;

    for (int bstart = blockIdx.x * PPB; bstart < cnt; bstart += FBLK * PPB) {
        const int bend = min(bstart + PPB, cnt);

        for (int g0 = bstart + warp * 4; g0 < bend; g0 += 32) {
            const int nv = min(4, bend - g0);
            float2 fv[4];
            int    pts[4];

            #pragma unroll
            for (int p = 0; p < 4; p++) {
                if (p < nv) {
                    pts[p] = binp[g0 + p];
                    fv[p]  = ((const float2*)(feats + (size_t)pts[p] * C_IN))[lane];
                } else {
                    fv[p] = make_float2(0.f, 0.f);
                    pts[p] = 0;
                }
            }

            unsigned long long accA[4], accB[4];
            #pragma unroll
            for (int p = 0; p < 4; p++) { accA[p] = 0ull; accB[p] = 0ull; }

            #pragma unroll
            for (int c = 0; c < C_IN; c++) {
                float4 k = *(const float4*)(Ks + c * C_OUT + 4 * lane);
                unsigned long long kA = pack2(k.x, k.y);
                unsigned long long kB = pack2(k.z, k.w);
                #pragma unroll
                for (int p = 0; p < 4; p++) {
                    float f = __shfl_sync(0xffffffffu,
                                          (c & 1) ? fv[p].y : fv[p].x, c >> 1);
                    unsigned long long ff = pack2(f, f);
                    accA[p] = fma2(ff, kA, accA[p]);
                    accB[p] = fma2(ff, kB, accB[p]);
                }
            }

            #pragma unroll
            for (int p = 0; p < 4; p++) {
                if (p < nv) {
                    float4 v;
                    unpack2(accA[p], v.x, v.y);
                    unpack2(accB[p], v.z, v.w);
                    *(float4*)(d_fbuf + (size_t)pts[p] * C_OUT + 4 * lane) = v;
                }
            }
        }
    }
    cudaTriggerProgrammaticLaunchCompletion();
}

// ---------------------------------------------------------------------------
// Phase 2 (R7 shape): row-owner scatter with sparse z-major tile, 8 channels
// per block. Grid (NCG, NBX), 18.4 KB smem -> 8 blocks/SM, full occupancy.
// Pass 1 (zmask + touched-cell zeroing, reads only k_bin output); gridsync;
// pass 2 smem-atomic adds from f_buf; masked coalesced streaming readout.
// Done-counter: 16th finisher of a bin resets curX/doneX/curH.
// ---------------------------------------------------------------------------
__global__ __launch_bounds__(256)
void k_bev(float* __restrict__ out)
{
    __shared__ float tile[512 * ZPITCH];             // 18.4 KB
    __shared__ unsigned int zmask[16];               // 512 bits

    const int bin = blockIdx.y;
    const int c0  = blockIdx.x << 3;
    const int b   = bin >> 9;
    const int x   = bin & 511;
    const int tid  = threadIdx.x;
    const int qwid = tid >> 3;                       // 0..31
    const int ql   = tid & 7;

    if (tid < 16) zmask[tid] = 0u;
    __syncthreads();

    int cnt = d_curX[bin];
    if (cnt > CAPX) cnt = CAPX;
    const int* binp = d_binX + bin * CAPX;

    // pass 1: mark + zero touched cells (races write 0 -> benign)
    for (int p = qwid; p < cnt; p += 32) {
        int z = binp[p] & 511;
        if (ql == 0) atomicOr(&zmask[z >> 5], 1u << (z & 31));
        tile[z * ZPITCH + ql] = 0.f;
    }

    cudaGridDependencySynchronize();                 // wait for k_feat's f_buf
    __syncthreads();

    // pass 2: accumulate (quarter-warp = one point, lane = channel)
    for (int p = qwid; p < cnt; p += 32) {
        int e  = binp[p];
        int pt = e >> 9;
        int z  = e & 511;
        float v = d_fbuf[(size_t)pt * C_OUT + c0 + ql];
        atomicAdd(&tile[z * ZPITCH + ql], v);
    }
    __syncthreads();

    // readout: out[b][c0+c][x][z], 8 rows of 512 floats, coalesced stores.
    float4* o4 = (float4*)(out + (((size_t)(b * C_OUT + c0)) * BEV_H + x) * BEV_W);
    #pragma unroll
    for (int i = tid; i < CG * 128; i += 256) {
        int c = i >> 7;                              // channel within group
        int j = i & 127;                             // 4-z chunk
        float4 v = make_float4(0.f, 0.f, 0.f, 0.f);
        unsigned int bits = (zmask[j >> 3] >> ((j & 7) * 4)) & 0xFu;
        if (bits) {
            int zb = 4 * j;
            if (bits & 1u) v.x = tile[(zb    ) * ZPITCH + c];
            if (bits & 2u) v.y = tile[(zb + 1) * ZPITCH + c];
            if (bits & 4u) v.z = tile[(zb + 2) * ZPITCH + c];
            if (bits & 8u) v.w = tile[(zb + 3) * ZPITCH + c];
        }
        __stcs(&o4[(size_t)c * (HW / 4) + j], v);
    }

    // last of this bin's 16 blocks resets its cursors (all have read cnt,
    // and k_feat is fully complete past the gridsync above)
    if (tid == 0) {
        int dn = atomicAdd(&d_doneX[bin], 1);
        if (dn == NCG - 1) {
            d_curX[bin] = 0;
            d_doneX[bin] = 0;
            if (bin < NKER) d_curH[bin] = 0;
        }
    }
}

// ---------------------------------------------------------------------------
// Launch (PDL chain: k_bin -> k_feat -> k_bev)
// ---------------------------------------------------------------------------
extern "C" void kernel_launch(void* const* d_in, const int* in_sizes, int n_in,
                              void* d_out, int out_size)
{
    const int*   coords = (const int*)  d_in[0];   // [N,4] int32
    const float* feats  = (const float*)d_in[1];   // [N,64] f32
    const float* kern   = (const float*)d_in[2];   // [16,64,128] f32
    float*       out    = (float*)d_out;           // [2,128,512,512] f32

    int n = in_sizes[0] / 4;
    if (n > MAXN) n = MAXN;

    k_bin<<<(n + 1023) / 1024, 512>>>(coords, n);

    cudaLaunchAttribute attrs[1];
    attrs[0].id = cudaLaunchAttributeProgrammaticStreamSerialization;
    attrs[0].val.programmaticStreamSerializationAllowed = 1;

    {   // k_feat with PDL (smem preload overlaps k_bin tail)
        cudaLaunchConfig_t cfg = {};
        cfg.gridDim  = dim3(FBLK, NKER);
        cfg.blockDim = dim3(256);
        cfg.stream   = 0;
        cfg.attrs    = attrs;
        cfg.numAttrs = 1;
        cudaLaunchKernelEx(&cfg, k_feat, feats, kern);
    }
    {   // k_bev with PDL
        cudaLaunchConfig_t cfg = {};
        cfg.gridDim  = dim3(NCG, NBX);
        cfg.blockDim = dim3(256);
        cfg.stream   = 0;
        cfg.attrs    = attrs;
        cfg.numAttrs = 1;
        cudaLaunchKernelEx(&cfg, k_bev, out);
    }
}